// round 1
// baseline (speedup 1.0000x reference)
#include <cuda_runtime.h>
#include <math.h>

#define D_MODEL 1024
#define NUM_HEADS 16
#define D_K 64
#define D_FF 4096
#define BATCH 2
#define SEQ 2048
#define TOK (BATCH*SEQ)   // 4096

// ---------------- scratch (static device globals; no runtime allocation) ----------
__device__ float g_q[(size_t)TOK*D_MODEL];
__device__ float g_k[(size_t)TOK*D_MODEL];
__device__ float g_v[(size_t)TOK*D_MODEL];
__device__ float g_ctx[(size_t)TOK*D_MODEL];
__device__ float g_y[(size_t)TOK*D_MODEL];
__device__ float g_h[(size_t)TOK*D_MODEL];
__device__ float g_ff[(size_t)TOK*D_FF];

// ---------------- batched/strided SGEMM: C = alpha*(A op(B)) + bias, opt ReLU ------
// A: [M,K] row-major (lda). If TB==false: B is [K,N] row-major (ldb).
// If TB==true:  B is [N,K] row-major (ldb)  (i.e. C = A * B^T).
// Batch offset for z = b*NUM_HEADS + h: ptr += b*s?b + h*s?h.
template<bool TB, bool RELU>
__launch_bounds__(256)
__global__ void sgemm_k(const float* __restrict__ A, const float* __restrict__ Bm,
                        const float* __restrict__ bias, float* __restrict__ C,
                        int M, int N, int K, int lda, int ldb, int ldc,
                        long sAb, long sAh, long sBb, long sBh, long sCb, long sCh,
                        float alpha)
{
    __shared__ float As[8][128];
    __shared__ float Bs[8][128];

    const int bz = blockIdx.z;
    const int bb = bz / NUM_HEADS, hh = bz % NUM_HEADS;
    A  += (long)bb*sAb + (long)hh*sAh;
    Bm += (long)bb*sBb + (long)hh*sBh;
    C  += (long)bb*sCb + (long)hh*sCh;

    const int tid = threadIdx.x;
    const int tx = tid & 15, ty = tid >> 4;
    const int row0 = blockIdx.y * 128, col0 = blockIdx.x * 128;

    float acc[8][8];
#pragma unroll
    for (int i = 0; i < 8; i++)
#pragma unroll
        for (int j = 0; j < 8; j++) acc[i][j] = 0.f;

    const int ar = tid >> 1, ac = (tid & 1) << 2;        // A tile: 128 rows x 8 k
    const int brNN = tid >> 5, bcNN = (tid & 31) << 2;   // B NN:   8 k x 128 cols
    const int bnNT = tid >> 1, bkNT = (tid & 1) << 2;    // B NT:   128 n x 8 k

    for (int kt = 0; kt < K; kt += 8) {
        // --- load A tile (transposed into As[k][m]) ---
        float4 a4 = make_float4(0.f, 0.f, 0.f, 0.f);
        {
            int gr = row0 + ar;
            if (gr < M) a4 = *(const float4*)(A + (long)gr * lda + kt + ac);
        }
        As[ac + 0][ar] = a4.x; As[ac + 1][ar] = a4.y;
        As[ac + 2][ar] = a4.z; As[ac + 3][ar] = a4.w;

        // --- load B tile into Bs[k][n] ---
        if (!TB) {
            float4 b4 = make_float4(0.f, 0.f, 0.f, 0.f);
            int gc = col0 + bcNN;
            if (gc < N) b4 = *(const float4*)(Bm + (long)(kt + brNN) * ldb + gc);
            *(float4*)&Bs[brNN][bcNN] = b4;
        } else {
            float4 b4 = make_float4(0.f, 0.f, 0.f, 0.f);
            int gn = col0 + bnNT;
            if (gn < N) b4 = *(const float4*)(Bm + (long)gn * ldb + kt + bkNT);
            Bs[bkNT + 0][bnNT] = b4.x; Bs[bkNT + 1][bnNT] = b4.y;
            Bs[bkNT + 2][bnNT] = b4.z; Bs[bkNT + 3][bnNT] = b4.w;
        }
        __syncthreads();

#pragma unroll
        for (int k = 0; k < 8; k++) {
            float ra[8], rb[8];
#pragma unroll
            for (int i = 0; i < 8; i++) ra[i] = As[k][ty * 8 + i];
#pragma unroll
            for (int j = 0; j < 8; j++) rb[j] = Bs[k][tx * 8 + j];
#pragma unroll
            for (int i = 0; i < 8; i++)
#pragma unroll
                for (int j = 0; j < 8; j++)
                    acc[i][j] = fmaf(ra[i], rb[j], acc[i][j]);
        }
        __syncthreads();
    }

    // --- epilogue ---
#pragma unroll
    for (int i = 0; i < 8; i++) {
        int r = row0 + ty * 8 + i;
        if (r >= M) continue;
#pragma unroll
        for (int j = 0; j < 8; j++) {
            int c = col0 + tx * 8 + j;
            if (c >= N) continue;
            float v = acc[i][j] * alpha;
            if (bias) v += bias[c];
            if (RELU) v = fmaxf(v, 0.f);
            C[(long)r * ldc + c] = v;
        }
    }
}

// ---------------- masked softmax over rows of length SEQ (in-place) ----------------
// grid = B*H*S blocks, 256 threads; 8 elements per thread.
__launch_bounds__(256)
__global__ void softmax_k(float* __restrict__ attn, const int* __restrict__ mask)
{
    const long row = blockIdx.x;
    const int b = (int)(row / ((long)NUM_HEADS * SEQ));
    float* p = attn + row * SEQ;
    const int* m = mask + (long)b * SEQ;
    const int tid = threadIdx.x;

    __shared__ float sred[8];
    __shared__ float sbc;

    float vals[8];
    float mx = -1e30f;
#pragma unroll
    for (int t = 0; t < 8; t++) {
        int j = tid + t * 256;
        float vv = p[j];
        if (m[j] == 0) vv = -1e9f;
        vals[t] = vv;
        mx = fmaxf(mx, vv);
    }
#pragma unroll
    for (int o = 16; o; o >>= 1) mx = fmaxf(mx, __shfl_xor_sync(0xffffffffu, mx, o));
    if ((tid & 31) == 0) sred[tid >> 5] = mx;
    __syncthreads();
    if (tid == 0) {
        float r = sred[0];
#pragma unroll
        for (int i = 1; i < 8; i++) r = fmaxf(r, sred[i]);
        sbc = r;
    }
    __syncthreads();
    mx = sbc;

    float sum = 0.f;
#pragma unroll
    for (int t = 0; t < 8; t++) {
        vals[t] = __expf(vals[t] - mx);
        sum += vals[t];
    }
#pragma unroll
    for (int o = 16; o; o >>= 1) sum += __shfl_xor_sync(0xffffffffu, sum, o);
    __syncthreads();                    // protect sred/sbc reuse
    if ((tid & 31) == 0) sred[tid >> 5] = sum;
    __syncthreads();
    if (tid == 0) {
        float r = 0.f;
#pragma unroll
        for (int i = 0; i < 8; i++) r += sred[i];
        sbc = 1.f / r;
    }
    __syncthreads();
    const float inv = sbc;
#pragma unroll
    for (int t = 0; t < 8; t++) {
        int j = tid + t * 256;
        p[j] = vals[t] * inv;
    }
}

// ---------------- out = LayerNorm(a + b) * g + be, row length D_MODEL --------------
// grid = TOK blocks, 256 threads; 4 elements per thread.
__launch_bounds__(256)
__global__ void add_ln_k(const float* __restrict__ a, const float* __restrict__ bres,
                         const float* __restrict__ g, const float* __restrict__ be,
                         float* __restrict__ outp)
{
    const long row = blockIdx.x;
    const float* pa = a + row * D_MODEL;
    const float* pb = bres + row * D_MODEL;
    float* po = outp + row * D_MODEL;
    const int tid = threadIdx.x;

    __shared__ float sred[8];
    __shared__ float sbc;

    float v[4];
    float s = 0.f;
#pragma unroll
    for (int t = 0; t < 4; t++) {
        int c = tid + t * 256;
        v[t] = pa[c] + pb[c];
        s += v[t];
    }
#pragma unroll
    for (int o = 16; o; o >>= 1) s += __shfl_xor_sync(0xffffffffu, s, o);
    if ((tid & 31) == 0) sred[tid >> 5] = s;
    __syncthreads();
    if (tid == 0) {
        float r = 0.f;
#pragma unroll
        for (int i = 0; i < 8; i++) r += sred[i];
        sbc = r * (1.f / D_MODEL);
    }
    __syncthreads();
    const float mu = sbc;

    float q = 0.f;
#pragma unroll
    for (int t = 0; t < 4; t++) {
        float d = v[t] - mu;
        q += d * d;
    }
#pragma unroll
    for (int o = 16; o; o >>= 1) q += __shfl_xor_sync(0xffffffffu, q, o);
    __syncthreads();
    if ((tid & 31) == 0) sred[tid >> 5] = q;
    __syncthreads();
    if (tid == 0) {
        float r = 0.f;
#pragma unroll
        for (int i = 0; i < 8; i++) r += sred[i];
        sbc = rsqrtf(r * (1.f / D_MODEL) + 1e-5f);
    }
    __syncthreads();
    const float rstd = sbc;

#pragma unroll
    for (int t = 0; t < 4; t++) {
        int c = tid + t * 256;
        po[c] = (v[t] - mu) * rstd * g[c] + be[c];
    }
}

// -----------------------------------------------------------------------------------
extern "C" void kernel_launch(void* const* d_in, const int* in_sizes, int n_in,
                              void* d_out, int out_size)
{
    (void)in_sizes; (void)n_in; (void)out_size;
    const float* x   = (const float*)d_in[0];
    const int*   mask= (const int*)  d_in[1];
    const float* Wq  = (const float*)d_in[2];
    const float* bq  = (const float*)d_in[3];
    const float* Wk  = (const float*)d_in[4];
    const float* bk  = (const float*)d_in[5];
    const float* Wv  = (const float*)d_in[6];
    const float* bv  = (const float*)d_in[7];
    const float* Wo  = (const float*)d_in[8];
    const float* bo  = (const float*)d_in[9];
    const float* g1  = (const float*)d_in[10];
    const float* be1 = (const float*)d_in[11];
    const float* W1  = (const float*)d_in[12];
    const float* b1  = (const float*)d_in[13];
    const float* W2  = (const float*)d_in[14];
    const float* b2  = (const float*)d_in[15];
    const float* g2  = (const float*)d_in[16];
    const float* be2 = (const float*)d_in[17];

    float* out  = (float*)d_out;
    float* attn = out + (size_t)TOK * D_MODEL;   // tuple (out, attn) flattened in order

    float *q, *k, *v, *ctx, *y, *h, *ff;
    cudaGetSymbolAddress((void**)&q,   g_q);
    cudaGetSymbolAddress((void**)&k,   g_k);
    cudaGetSymbolAddress((void**)&v,   g_v);
    cudaGetSymbolAddress((void**)&ctx, g_ctx);
    cudaGetSymbolAddress((void**)&y,   g_y);
    cudaGetSymbolAddress((void**)&h,   g_h);
    cudaGetSymbolAddress((void**)&ff,  g_ff);

    const dim3 blk(256);
    const long SD = (long)SEQ * D_MODEL;   // per-batch stride of [B,S,D]
    const long SS = (long)SEQ * SEQ;       // per-head stride of [B,H,S,S]

    // Q, K, V projections: [4096,1024] = x @ W + b
    sgemm_k<false, false><<<dim3(8, 32, 1), blk>>>(x, Wq, bq, q, TOK, D_MODEL, D_MODEL,
        D_MODEL, D_MODEL, D_MODEL, 0, 0, 0, 0, 0, 0, 1.f);
    sgemm_k<false, false><<<dim3(8, 32, 1), blk>>>(x, Wk, bk, k, TOK, D_MODEL, D_MODEL,
        D_MODEL, D_MODEL, D_MODEL, 0, 0, 0, 0, 0, 0, 1.f);
    sgemm_k<false, false><<<dim3(8, 32, 1), blk>>>(x, Wv, bv, v, TOK, D_MODEL, D_MODEL,
        D_MODEL, D_MODEL, D_MODEL, 0, 0, 0, 0, 0, 0, 1.f);

    // scores = (Qh @ Kh^T) / sqrt(64), batched over B*H, written raw into attn region
    sgemm_k<true, false><<<dim3(16, 16, BATCH * NUM_HEADS), blk>>>(
        q, k, nullptr, attn, SEQ, SEQ, D_K,
        D_MODEL, D_MODEL, SEQ,
        SD, D_K, SD, D_K, (long)NUM_HEADS * SS, SS, 0.125f);

    // masked softmax, in place (attn is a final output)
    softmax_k<<<BATCH * NUM_HEADS * SEQ, blk>>>(attn, mask);

    // ctx = attn @ Vh, batched over B*H, written interleaved into [B,S,D]
    sgemm_k<false, false><<<dim3(1, 16, BATCH * NUM_HEADS), blk>>>(
        attn, v, nullptr, ctx, SEQ, D_K, SEQ,
        SEQ, D_MODEL, D_MODEL,
        (long)NUM_HEADS * SS, SS, SD, D_K, SD, D_K, 1.f);

    // attn_out = ctx @ Wo + bo
    sgemm_k<false, false><<<dim3(8, 32, 1), blk>>>(ctx, Wo, bo, y, TOK, D_MODEL, D_MODEL,
        D_MODEL, D_MODEL, D_MODEL, 0, 0, 0, 0, 0, 0, 1.f);

    // h = LN(x + attn_out)
    add_ln_k<<<TOK, blk>>>(x, y, g1, be1, h);

    // ff = relu(h @ W1 + b1)
    sgemm_k<false, true><<<dim3(32, 32, 1), blk>>>(h, W1, b1, ff, TOK, D_FF, D_MODEL,
        D_MODEL, D_FF, D_FF, 0, 0, 0, 0, 0, 0, 1.f);

    // y = ff @ W2 + b2
    sgemm_k<false, false><<<dim3(8, 32, 1), blk>>>(ff, W2, b2, y, TOK, D_MODEL, D_FF,
        D_FF, D_MODEL, D_MODEL, 0, 0, 0, 0, 0, 0, 1.f);

    // out = LN(h + y)
    add_ln_k<<<TOK, blk>>>(h, y, g2, be2, out);
}

// round 2
// speedup vs baseline: 1.0008x; 1.0008x over previous
#include <cuda_runtime.h>
#include <math.h>

#define D_MODEL 1024
#define NUM_HEADS 16
#define D_K 64
#define D_FF 4096
#define BATCH 2
#define SEQ 2048
#define TOK (BATCH*SEQ)   // 4096

// ---------------- scratch (static device globals; no runtime allocation) ----------
__device__ float g_q[(size_t)TOK*D_MODEL];
__device__ float g_k[(size_t)TOK*D_MODEL];
__device__ float g_v[(size_t)TOK*D_MODEL];
__device__ float g_ctx[(size_t)TOK*D_MODEL];
__device__ float g_y[(size_t)TOK*D_MODEL];
__device__ float g_h[(size_t)TOK*D_MODEL];
__device__ float g_ff[(size_t)TOK*D_FF];

// ---------------- batched/strided SGEMM: C = alpha*(A op(B)) + bias, opt ReLU ------
// A: [M,K] row-major (lda). If TB==false: B is [K,N] row-major (ldb).
// If TB==true:  B is [N,K] row-major (ldb)  (i.e. C = A * B^T).
// Batch offset for z = b*NUM_HEADS + h: ptr += b*s?b + h*s?h.
template<bool TB, bool RELU>
__launch_bounds__(256)
__global__ void sgemm_k(const float* __restrict__ A, const float* __restrict__ Bm,
                        const float* __restrict__ bias, float* __restrict__ C,
                        int M, int N, int K, int lda, int ldb, int ldc,
                        long sAb, long sAh, long sBb, long sBh, long sCb, long sCh,
                        float alpha)
{
    __shared__ float As[8][128];
    __shared__ float Bs[8][128];

    const int bz = blockIdx.z;
    const int bb = bz / NUM_HEADS, hh = bz % NUM_HEADS;
    A  += (long)bb*sAb + (long)hh*sAh;
    Bm += (long)bb*sBb + (long)hh*sBh;
    C  += (long)bb*sCb + (long)hh*sCh;

    const int tid = threadIdx.x;
    const int tx = tid & 15, ty = tid >> 4;
    const int row0 = blockIdx.y * 128, col0 = blockIdx.x * 128;

    float acc[8][8];
#pragma unroll
    for (int i = 0; i < 8; i++)
#pragma unroll
        for (int j = 0; j < 8; j++) acc[i][j] = 0.f;

    const int ar = tid >> 1, ac = (tid & 1) << 2;        // A tile: 128 rows x 8 k
    const int brNN = tid >> 5, bcNN = (tid & 31) << 2;   // B NN:   8 k x 128 cols
    const int bnNT = tid >> 1, bkNT = (tid & 1) << 2;    // B NT:   128 n x 8 k

    for (int kt = 0; kt < K; kt += 8) {
        // --- load A tile (transposed into As[k][m]) ---
        float4 a4 = make_float4(0.f, 0.f, 0.f, 0.f);
        {
            int gr = row0 + ar;
            if (gr < M) a4 = *(const float4*)(A + (long)gr * lda + kt + ac);
        }
        As[ac + 0][ar] = a4.x; As[ac + 1][ar] = a4.y;
        As[ac + 2][ar] = a4.z; As[ac + 3][ar] = a4.w;

        // --- load B tile into Bs[k][n] ---
        if (!TB) {
            float4 b4 = make_float4(0.f, 0.f, 0.f, 0.f);
            int gc = col0 + bcNN;
            if (gc < N) b4 = *(const float4*)(Bm + (long)(kt + brNN) * ldb + gc);
            *(float4*)&Bs[brNN][bcNN] = b4;
        } else {
            float4 b4 = make_float4(0.f, 0.f, 0.f, 0.f);
            int gn = col0 + bnNT;
            if (gn < N) b4 = *(const float4*)(Bm + (long)gn * ldb + kt + bkNT);
            Bs[bkNT + 0][bnNT] = b4.x; Bs[bkNT + 1][bnNT] = b4.y;
            Bs[bkNT + 2][bnNT] = b4.z; Bs[bkNT + 3][bnNT] = b4.w;
        }
        __syncthreads();

#pragma unroll
        for (int k = 0; k < 8; k++) {
            float ra[8], rb[8];
#pragma unroll
            for (int i = 0; i < 8; i++) ra[i] = As[k][ty * 8 + i];
#pragma unroll
            for (int j = 0; j < 8; j++) rb[j] = Bs[k][tx * 8 + j];
#pragma unroll
            for (int i = 0; i < 8; i++)
#pragma unroll
                for (int j = 0; j < 8; j++)
                    acc[i][j] = fmaf(ra[i], rb[j], acc[i][j]);
        }
        __syncthreads();
    }

    // --- epilogue ---
#pragma unroll
    for (int i = 0; i < 8; i++) {
        int r = row0 + ty * 8 + i;
        if (r >= M) continue;
#pragma unroll
        for (int j = 0; j < 8; j++) {
            int c = col0 + tx * 8 + j;
            if (c >= N) continue;
            float v = acc[i][j] * alpha;
            if (bias) v += bias[c];
            if (RELU) v = fmaxf(v, 0.f);
            C[(long)r * ldc + c] = v;
        }
    }
}

// ---------------- masked softmax over rows of length SEQ (in-place) ----------------
// grid = B*H*S blocks, 256 threads; 8 elements per thread.
__launch_bounds__(256)
__global__ void softmax_k(float* __restrict__ attn, const int* __restrict__ mask)
{
    const long row = blockIdx.x;
    const int b = (int)(row / ((long)NUM_HEADS * SEQ));
    float* p = attn + row * SEQ;
    const int* m = mask + (long)b * SEQ;
    const int tid = threadIdx.x;

    __shared__ float sred[8];
    __shared__ float sbc;

    float vals[8];
    float mx = -1e30f;
#pragma unroll
    for (int t = 0; t < 8; t++) {
        int j = tid + t * 256;
        float vv = p[j];
        if (m[j] == 0) vv = -1e9f;
        vals[t] = vv;
        mx = fmaxf(mx, vv);
    }
#pragma unroll
    for (int o = 16; o; o >>= 1) mx = fmaxf(mx, __shfl_xor_sync(0xffffffffu, mx, o));
    if ((tid & 31) == 0) sred[tid >> 5] = mx;
    __syncthreads();
    if (tid == 0) {
        float r = sred[0];
#pragma unroll
        for (int i = 1; i < 8; i++) r = fmaxf(r, sred[i]);
        sbc = r;
    }
    __syncthreads();
    mx = sbc;

    float sum = 0.f;
#pragma unroll
    for (int t = 0; t < 8; t++) {
        vals[t] = __expf(vals[t] - mx);
        sum += vals[t];
    }
#pragma unroll
    for (int o = 16; o; o >>= 1) sum += __shfl_xor_sync(0xffffffffu, sum, o);
    __syncthreads();                    // protect sred/sbc reuse
    if ((tid & 31) == 0) sred[tid >> 5] = sum;
    __syncthreads();
    if (tid == 0) {
        float r = 0.f;
#pragma unroll
        for (int i = 0; i < 8; i++) r += sred[i];
        sbc = 1.f / r;
    }
    __syncthreads();
    const float inv = sbc;
#pragma unroll
    for (int t = 0; t < 8; t++) {
        int j = tid + t * 256;
        p[j] = vals[t] * inv;
    }
}

// ---------------- out = LayerNorm(a + b) * g + be, row length D_MODEL --------------
// grid = TOK blocks, 256 threads; 4 elements per thread.
__launch_bounds__(256)
__global__ void add_ln_k(const float* __restrict__ a, const float* __restrict__ bres,
                         const float* __restrict__ g, const float* __restrict__ be,
                         float* __restrict__ outp)
{
    const long row = blockIdx.x;
    const float* pa = a + row * D_MODEL;
    const float* pb = bres + row * D_MODEL;
    float* po = outp + row * D_MODEL;
    const int tid = threadIdx.x;

    __shared__ float sred[8];
    __shared__ float sbc;

    float v[4];
    float s = 0.f;
#pragma unroll
    for (int t = 0; t < 4; t++) {
        int c = tid + t * 256;
        v[t] = pa[c] + pb[c];
        s += v[t];
    }
#pragma unroll
    for (int o = 16; o; o >>= 1) s += __shfl_xor_sync(0xffffffffu, s, o);
    if ((tid & 31) == 0) sred[tid >> 5] = s;
    __syncthreads();
    if (tid == 0) {
        float r = 0.f;
#pragma unroll
        for (int i = 0; i < 8; i++) r += sred[i];
        sbc = r * (1.f / D_MODEL);
    }
    __syncthreads();
    const float mu = sbc;

    float q = 0.f;
#pragma unroll
    for (int t = 0; t < 4; t++) {
        float d = v[t] - mu;
        q += d * d;
    }
#pragma unroll
    for (int o = 16; o; o >>= 1) q += __shfl_xor_sync(0xffffffffu, q, o);
    __syncthreads();
    if ((tid & 31) == 0) sred[tid >> 5] = q;
    __syncthreads();
    if (tid == 0) {
        float r = 0.f;
#pragma unroll
        for (int i = 0; i < 8; i++) r += sred[i];
        sbc = rsqrtf(r * (1.f / D_MODEL) + 1e-5f);
    }
    __syncthreads();
    const float rstd = sbc;

#pragma unroll
    for (int t = 0; t < 4; t++) {
        int c = tid + t * 256;
        po[c] = (v[t] - mu) * rstd * g[c] + be[c];
    }
}

// -----------------------------------------------------------------------------------
extern "C" void kernel_launch(void* const* d_in, const int* in_sizes, int n_in,
                              void* d_out, int out_size)
{
    (void)in_sizes; (void)n_in; (void)out_size;
    const float* x   = (const float*)d_in[0];
    const int*   mask= (const int*)  d_in[1];
    const float* Wq  = (const float*)d_in[2];
    const float* bq  = (const float*)d_in[3];
    const float* Wk  = (const float*)d_in[4];
    const float* bk  = (const float*)d_in[5];
    const float* Wv  = (const float*)d_in[6];
    const float* bv  = (const float*)d_in[7];
    const float* Wo  = (const float*)d_in[8];
    const float* bo  = (const float*)d_in[9];
    const float* g1  = (const float*)d_in[10];
    const float* be1 = (const float*)d_in[11];
    const float* W1  = (const float*)d_in[12];
    const float* b1  = (const float*)d_in[13];
    const float* W2  = (const float*)d_in[14];
    const float* b2  = (const float*)d_in[15];
    const float* g2  = (const float*)d_in[16];
    const float* be2 = (const float*)d_in[17];

    float* out  = (float*)d_out;
    float* attn = out + (size_t)TOK * D_MODEL;   // tuple (out, attn) flattened in order

    float *q, *k, *v, *ctx, *y, *h, *ff;
    cudaGetSymbolAddress((void**)&q,   g_q);
    cudaGetSymbolAddress((void**)&k,   g_k);
    cudaGetSymbolAddress((void**)&v,   g_v);
    cudaGetSymbolAddress((void**)&ctx, g_ctx);
    cudaGetSymbolAddress((void**)&y,   g_y);
    cudaGetSymbolAddress((void**)&h,   g_h);
    cudaGetSymbolAddress((void**)&ff,  g_ff);

    const dim3 blk(256);
    const long SD = (long)SEQ * D_MODEL;   // per-batch stride of [B,S,D]
    const long SS = (long)SEQ * SEQ;       // per-head stride of [B,H,S,S]

    // Q, K, V projections: [4096,1024] = x @ W + b
    sgemm_k<false, false><<<dim3(8, 32, 1), blk>>>(x, Wq, bq, q, TOK, D_MODEL, D_MODEL,
        D_MODEL, D_MODEL, D_MODEL, 0, 0, 0, 0, 0, 0, 1.f);
    sgemm_k<false, false><<<dim3(8, 32, 1), blk>>>(x, Wk, bk, k, TOK, D_MODEL, D_MODEL,
        D_MODEL, D_MODEL, D_MODEL, 0, 0, 0, 0, 0, 0, 1.f);
    sgemm_k<false, false><<<dim3(8, 32, 1), blk>>>(x, Wv, bv, v, TOK, D_MODEL, D_MODEL,
        D_MODEL, D_MODEL, D_MODEL, 0, 0, 0, 0, 0, 0, 1.f);

    // scores = (Qh @ Kh^T) / sqrt(64), batched over B*H, written raw into attn region
    sgemm_k<true, false><<<dim3(16, 16, BATCH * NUM_HEADS), blk>>>(
        q, k, nullptr, attn, SEQ, SEQ, D_K,
        D_MODEL, D_MODEL, SEQ,
        SD, D_K, SD, D_K, (long)NUM_HEADS * SS, SS, 0.125f);

    // masked softmax, in place (attn is a final output)
    softmax_k<<<BATCH * NUM_HEADS * SEQ, blk>>>(attn, mask);

    // ctx = attn @ Vh, batched over B*H, written interleaved into [B,S,D]
    sgemm_k<false, false><<<dim3(1, 16, BATCH * NUM_HEADS), blk>>>(
        attn, v, nullptr, ctx, SEQ, D_K, SEQ,
        SEQ, D_MODEL, D_MODEL,
        (long)NUM_HEADS * SS, SS, SD, D_K, SD, D_K, 1.f);

    // attn_out = ctx @ Wo + bo
    sgemm_k<false, false><<<dim3(8, 32, 1), blk>>>(ctx, Wo, bo, y, TOK, D_MODEL, D_MODEL,
        D_MODEL, D_MODEL, D_MODEL, 0, 0, 0, 0, 0, 0, 1.f);

    // h = LN(x + attn_out)
    add_ln_k<<<TOK, blk>>>(x, y, g1, be1, h);

    // ff = relu(h @ W1 + b1)
    sgemm_k<false, true><<<dim3(32, 32, 1), blk>>>(h, W1, b1, ff, TOK, D_FF, D_MODEL,
        D_MODEL, D_FF, D_FF, 0, 0, 0, 0, 0, 0, 1.f);

    // y = ff @ W2 + b2
    sgemm_k<false, false><<<dim3(8, 32, 1), blk>>>(ff, W2, b2, y, TOK, D_MODEL, D_FF,
        D_FF, D_MODEL, D_MODEL, 0, 0, 0, 0, 0, 0, 1.f);

    // out = LN(h + y)
    add_ln_k<<<TOK, blk>>>(h, y, g2, be2, out);
}

// round 4
// speedup vs baseline: 2.2985x; 2.2967x over previous
#include <cuda_runtime.h>
#include <cuda_bf16.h>
#include <cstdint>
#include <math.h>

#define D_MODEL 1024
#define NUM_HEADS 16
#define D_K 64
#define D_FF 4096
#define BATCH 2
#define SEQ 2048
#define TOK (BATCH*SEQ)
#define BH (BATCH*NUM_HEADS)
typedef __nv_bfloat16 bf16;

// ---- scratch ----
__device__ bf16 g_xh[(size_t)TOK*D_MODEL], g_xl[(size_t)TOK*D_MODEL];
__device__ bf16 g_wqh[(size_t)D_MODEL*D_MODEL], g_wql[(size_t)D_MODEL*D_MODEL];
__device__ bf16 g_wkh[(size_t)D_MODEL*D_MODEL], g_wkl[(size_t)D_MODEL*D_MODEL];
__device__ bf16 g_wvh[(size_t)D_MODEL*D_MODEL], g_wvl[(size_t)D_MODEL*D_MODEL];
__device__ bf16 g_woh[(size_t)D_MODEL*D_MODEL], g_wol[(size_t)D_MODEL*D_MODEL];
__device__ bf16 g_w1h[(size_t)D_FF*D_MODEL],  g_w1l[(size_t)D_FF*D_MODEL];
__device__ bf16 g_w2h[(size_t)D_MODEL*D_FF],  g_w2l[(size_t)D_MODEL*D_FF];
__device__ bf16 g_qh[(size_t)TOK*D_MODEL], g_ql[(size_t)TOK*D_MODEL];
__device__ bf16 g_kh[(size_t)TOK*D_MODEL], g_kl[(size_t)TOK*D_MODEL];
__device__ bf16 g_vh[(size_t)TOK*D_MODEL], g_vl[(size_t)TOK*D_MODEL];
__device__ bf16 g_vth[(size_t)BH*D_K*SEQ], g_vtl[(size_t)BH*D_K*SEQ];
__device__ bf16 g_ah[(size_t)BH*SEQ*SEQ],  g_al[(size_t)BH*SEQ*SEQ];
__device__ bf16 g_ch[(size_t)TOK*D_MODEL], g_cl[(size_t)TOK*D_MODEL];
__device__ bf16 g_hh[(size_t)TOK*D_MODEL], g_hl[(size_t)TOK*D_MODEL];
__device__ bf16 g_ffh[(size_t)TOK*D_FF],   g_ffl[(size_t)TOK*D_FF];
__device__ float g_y[(size_t)TOK*D_MODEL];
__device__ float g_h[(size_t)TOK*D_MODEL];

// ---- helpers ----
__device__ __forceinline__ uint32_t smem_u32(const void* p){
    uint32_t a;
    asm("{ .reg .u64 t; cvta.to.shared.u64 t, %1; cvt.u32.u64 %0, t; }" : "=r"(a) : "l"(p));
    return a;
}
__device__ __forceinline__ void f2pair(float f, bf16& h, bf16& l){
    h = __float2bfloat16(f);
    l = __float2bfloat16(f - __bfloat162float(h));
}
#define CP16(d, s) asm volatile("cp.async.cg.shared.global [%0], [%1], 16;" :: "r"(d), "l"(s))
#define CP_COMMIT() asm volatile("cp.async.commit_group;" ::: "memory")
#define MMA(c, a, b0, b1) \
    asm volatile("mma.sync.aligned.m16n8k16.row.col.f32.bf16.bf16.f32 " \
        "{%0,%1,%2,%3},{%4,%5,%6,%7},{%8,%9},{%0,%1,%2,%3};" \
        : "+f"((c)[0]),"+f"((c)[1]),"+f"((c)[2]),"+f"((c)[3]) \
        : "r"((a)[0]),"r"((a)[1]),"r"((a)[2]),"r"((a)[3]),"r"(b0),"r"(b1))

// ---- conversions ----
__global__ void conv_pair_k(const float* __restrict__ s, bf16* __restrict__ h, bf16* __restrict__ l, long n){
    long i = (long)blockIdx.x*blockDim.x + threadIdx.x;
    if(i < n){ bf16 a,b; f2pair(s[i],a,b); h[i]=a; l[i]=b; }
}
__global__ void wtrans_k(const float* __restrict__ W, bf16* __restrict__ th, bf16* __restrict__ tl, int K, int N){
    __shared__ float t[32][33];
    int n0 = blockIdx.x*32, k0 = blockIdx.y*32;
#pragma unroll
    for(int r=0;r<4;r++) t[threadIdx.y+r*8][threadIdx.x] = W[(long)(k0+threadIdx.y+r*8)*N + n0+threadIdx.x];
    __syncthreads();
#pragma unroll
    for(int r=0;r<4;r++){
        int n = n0+threadIdx.y+r*8;
        bf16 a,b; f2pair(t[threadIdx.x][threadIdx.y+r*8],a,b);
        th[(long)n*K + k0+threadIdx.x]=a; tl[(long)n*K + k0+threadIdx.x]=b;
    }
}
__global__ void vtrans_k(const bf16* __restrict__ vh, const bf16* __restrict__ vl,
                         bf16* __restrict__ oth, bf16* __restrict__ otl){
    __shared__ bf16 th_[32][33], tl_[32][33];
    int bz = blockIdx.z, bb = bz/NUM_HEADS, hh = bz%NUM_HEADS;
    int s0 = blockIdx.x*32, n0 = blockIdx.y*32;
#pragma unroll
    for(int r=0;r<4;r++){
        long src = (long)(bb*SEQ + s0+threadIdx.y+r*8)*D_MODEL + hh*D_K + n0+threadIdx.x;
        th_[threadIdx.y+r*8][threadIdx.x] = vh[src];
        tl_[threadIdx.y+r*8][threadIdx.x] = vl[src];
    }
    __syncthreads();
#pragma unroll
    for(int r=0;r<4;r++){
        long dst = ((long)bz*D_K + n0+threadIdx.y+r*8)*SEQ + s0+threadIdx.x;
        oth[dst] = th_[threadIdx.x][threadIdx.y+r*8];
        otl[dst] = tl_[threadIdx.x][threadIdx.y+r*8];
    }
}

// ---- split-bf16 GEMM via mma.sync: C = alpha*A[M,K]*B[N,K]^T (+bias,+relu) ----
// 256 thr = 8 warps (4m x 2n). Block tile 128 x TN, BK=32, 2-stage cp.async pipe.
template<int TN, int OUT, bool RELU>
__global__ void __launch_bounds__(256) gemm_mma(
    const bf16* __restrict__ Ah, const bf16* __restrict__ Al,
    const bf16* __restrict__ Bh, const bf16* __restrict__ Bl,
    const float* __restrict__ bias,
    float* __restrict__ Cf, bf16* __restrict__ Ch, bf16* __restrict__ Cl,
    int K, int lda, int ldb, int ldc,
    long sAb, long sAhd, long sBb, long sBhd, long sCb, long sChd, float alpha)
{
    constexpr int PADK = 40;                 // 32 + 8 pad (bf16) -> conflict-free
    constexpr int SA = 128*PADK;             // one A matrix (bf16 elems)
    constexpr int SB = TN*PADK;
    constexpr int STG = 2*(SA+SB);           // hi+lo for A and B per stage
    constexpr int NTILES = TN/16;            // n-tiles per warp (8 or 4)
    constexpr int BCH = (TN==128) ? 2 : 1;   // B 16B chunks per thread per matrix

    extern __shared__ bf16 sm[];
    const int tid = threadIdx.x, wid = tid>>5, lane = tid&31;
    const int warp_m = wid & 3, warp_n = wid >> 2;
    const int g = lane>>2, t2 = (lane&3)*2;

    const int bz = blockIdx.z, bb = bz/NUM_HEADS, hh = bz%NUM_HEADS;
    Ah += bb*sAb + hh*sAhd;  Al += bb*sAb + hh*sAhd;
    Bh += bb*sBb + hh*sBhd;  Bl += bb*sBb + hh*sBhd;
    const long coff = bb*sCb + hh*sChd;
    const int row0 = blockIdx.y*128, col0 = blockIdx.x*TN;

    float acc[2][NTILES][4];
#pragma unroll
    for(int i=0;i<2;i++)
#pragma unroll
        for(int j=0;j<NTILES;j++)
#pragma unroll
            for(int e=0;e<4;e++) acc[i][j][e]=0.f;

    const int NT = K/32;

    auto issue = [&](int stage, int kb){
        bf16* st = sm + (stage&1)*STG;
#pragma unroll
        for(int c=0;c<2;c++){
            int cid = tid*2+c, r = cid>>2, k8 = (cid&3)*8;
            const bf16* sh = Ah + (long)(row0+r)*lda + kb + k8;
            const bf16* sl = Al + (long)(row0+r)*lda + kb + k8;
            CP16(smem_u32(st + r*PADK + k8), sh);
            CP16(smem_u32(st + SA + r*PADK + k8), sl);
        }
#pragma unroll
        for(int c=0;c<BCH;c++){
            int cid = tid*BCH+c, n = cid>>2, k8 = (cid&3)*8;
            const bf16* sh = Bh + (long)(col0+n)*ldb + kb + k8;
            const bf16* sl = Bl + (long)(col0+n)*ldb + kb + k8;
            CP16(smem_u32(st + 2*SA + n*PADK + k8), sh);
            CP16(smem_u32(st + 2*SA + SB + n*PADK + k8), sl);
        }
        CP_COMMIT();
    };

    auto compute = [&](int stage){
        const bf16* st  = sm + (stage&1)*STG;
        const bf16* sAh_ = st;
        const bf16* sAl_ = st + SA;
        const bf16* sBh_ = st + 2*SA;
        const bf16* sBl_ = st + 2*SA + SB;
#pragma unroll
        for(int ks=0; ks<2; ks++){
            const int kc = ks*16;
            uint32_t fAh[2][4], fAl[2][4];
#pragma unroll
            for(int mt=0; mt<2; mt++){
                int r = warp_m*32 + mt*16 + g;
                const bf16* ph = sAh_ + r*PADK + kc + t2;
                const bf16* pl = sAl_ + r*PADK + kc + t2;
                fAh[mt][0]=*(const uint32_t*)(ph);
                fAh[mt][1]=*(const uint32_t*)(ph+8*PADK);
                fAh[mt][2]=*(const uint32_t*)(ph+8);
                fAh[mt][3]=*(const uint32_t*)(ph+8*PADK+8);
                fAl[mt][0]=*(const uint32_t*)(pl);
                fAl[mt][1]=*(const uint32_t*)(pl+8*PADK);
                fAl[mt][2]=*(const uint32_t*)(pl+8);
                fAl[mt][3]=*(const uint32_t*)(pl+8*PADK+8);
            }
#pragma unroll
            for(int nt=0; nt<NTILES; nt++){
                int n = warp_n*(TN/2) + nt*8 + g;
                const bf16* pbh = sBh_ + n*PADK + kc + t2;
                const bf16* pbl = sBl_ + n*PADK + kc + t2;
                uint32_t bh0=*(const uint32_t*)(pbh), bh1=*(const uint32_t*)(pbh+8);
                uint32_t bl0=*(const uint32_t*)(pbl), bl1=*(const uint32_t*)(pbl+8);
#pragma unroll
                for(int mt=0; mt<2; mt++){
                    MMA(acc[mt][nt], fAh[mt], bh0, bh1);
                    MMA(acc[mt][nt], fAh[mt], bl0, bl1);
                    MMA(acc[mt][nt], fAl[mt], bh0, bh1);
                }
            }
        }
    };

    issue(0, 0);
    if(NT > 1) issue(1, 32);

    for(int i=0; i<NT; i++){
        if(i+1 < NT) asm volatile("cp.async.wait_group 1;" ::: "memory");
        else         asm volatile("cp.async.wait_group 0;" ::: "memory");
        __syncthreads();
        compute(i);
        if(i+2 < NT){
            __syncthreads();           // everyone done reading buffer i&1
            issue(i+2, (i+2)*32);
        }
    }

    // ---- epilogue ----
#pragma unroll
    for(int mt=0; mt<2; mt++){
#pragma unroll
        for(int nt=0; nt<NTILES; nt++){
            int r = row0 + warp_m*32 + mt*16 + g;
            int c = col0 + warp_n*(TN/2) + nt*8 + t2;
            float b0 = bias ? bias[c]   : 0.f;
            float b1 = bias ? bias[c+1] : 0.f;
#pragma unroll
            for(int half=0; half<2; half++){
                int rr = r + half*8;
                float v0 = acc[mt][nt][half*2+0]*alpha + b0;
                float v1 = acc[mt][nt][half*2+1]*alpha + b1;
                if(RELU){ v0 = fmaxf(v0,0.f); v1 = fmaxf(v1,0.f); }
                long idx = coff + (long)rr*ldc + c;
                if(OUT==0){
                    *(float2*)(Cf + idx) = make_float2(v0, v1);
                } else {
                    bf16 h0,l0,h1,l1; f2pair(v0,h0,l0); f2pair(v1,h1,l1);
                    *(__nv_bfloat162*)(Ch + idx) = __nv_bfloat162(h0, h1);
                    *(__nv_bfloat162*)(Cl + idx) = __nv_bfloat162(l0, l1);
                }
            }
        }
    }
}

// ---- softmax: in-place fp32 + bf16 pair out ----
__launch_bounds__(256)
__global__ void softmax_k(float* __restrict__ attn, const int* __restrict__ mask,
                          bf16* __restrict__ ah, bf16* __restrict__ al){
    const long row = blockIdx.x;
    const int b = (int)(row / ((long)NUM_HEADS*SEQ));
    float* p = attn + row*SEQ;
    const int* m = mask + (long)b*SEQ;
    const int tid = threadIdx.x;
    __shared__ float sred[8]; __shared__ float sbc;
    float vals[8]; float mx = -1e30f;
#pragma unroll
    for(int t=0;t<8;t++){ int j=tid+t*256; float vv=p[j]; if(m[j]==0) vv=-1e9f; vals[t]=vv; mx=fmaxf(mx,vv); }
#pragma unroll
    for(int o=16;o;o>>=1) mx = fmaxf(mx, __shfl_xor_sync(0xffffffffu, mx, o));
    if((tid&31)==0) sred[tid>>5]=mx;
    __syncthreads();
    if(tid==0){ float r=sred[0]; for(int i=1;i<8;i++) r=fmaxf(r,sred[i]); sbc=r; }
    __syncthreads();
    mx = sbc;
    float sum = 0.f;
#pragma unroll
    for(int t=0;t<8;t++){ vals[t]=__expf(vals[t]-mx); sum+=vals[t]; }
#pragma unroll
    for(int o=16;o;o>>=1) sum += __shfl_xor_sync(0xffffffffu, sum, o);
    __syncthreads();
    if((tid&31)==0) sred[tid>>5]=sum;
    __syncthreads();
    if(tid==0){ float r=0.f; for(int i=0;i<8;i++) r+=sred[i]; sbc=1.f/r; }
    __syncthreads();
    const float inv = sbc;
    bf16* pah = ah + row*SEQ; bf16* pal = al + row*SEQ;
#pragma unroll
    for(int t=0;t<8;t++){
        int j=tid+t*256; float v=vals[t]*inv; p[j]=v;
        bf16 h,l; f2pair(v,h,l); pah[j]=h; pal[j]=l;
    }
}

// ---- add + LN (+ optional pair out) ----
__launch_bounds__(256)
__global__ void add_ln_k(const float* __restrict__ a, const float* __restrict__ bres,
                         const float* __restrict__ g, const float* __restrict__ be,
                         float* __restrict__ outp, bf16* __restrict__ ph, bf16* __restrict__ pl){
    const long row = blockIdx.x;
    const float* pa = a + row*D_MODEL;
    const float* pb = bres + row*D_MODEL;
    const int tid = threadIdx.x;
    __shared__ float sred[8]; __shared__ float sbc;
    float v[4]; float s = 0.f;
#pragma unroll
    for(int t=0;t<4;t++){ int c=tid+t*256; v[t]=pa[c]+pb[c]; s+=v[t]; }
#pragma unroll
    for(int o=16;o;o>>=1) s += __shfl_xor_sync(0xffffffffu, s, o);
    if((tid&31)==0) sred[tid>>5]=s;
    __syncthreads();
    if(tid==0){ float r=0.f; for(int i=0;i<8;i++) r+=sred[i]; sbc=r*(1.f/D_MODEL); }
    __syncthreads();
    const float mu = sbc;
    float q = 0.f;
#pragma unroll
    for(int t=0;t<4;t++){ float d=v[t]-mu; q+=d*d; }
#pragma unroll
    for(int o=16;o;o>>=1) q += __shfl_xor_sync(0xffffffffu, q, o);
    __syncthreads();
    if((tid&31)==0) sred[tid>>5]=q;
    __syncthreads();
    if(tid==0){ float r=0.f; for(int i=0;i<8;i++) r+=sred[i]; sbc=rsqrtf(r*(1.f/D_MODEL)+1e-5f); }
    __syncthreads();
    const float rstd = sbc;
#pragma unroll
    for(int t=0;t<4;t++){
        int c = tid+t*256;
        float o = (v[t]-mu)*rstd*g[c] + be[c];
        outp[row*D_MODEL+c] = o;
        if(ph){ bf16 h,l; f2pair(o,h,l); ph[row*D_MODEL+c]=h; pl[row*D_MODEL+c]=l; }
    }
}

// -----------------------------------------------------------------------------------
extern "C" void kernel_launch(void* const* d_in, const int* in_sizes, int n_in,
                              void* d_out, int out_size)
{
    (void)in_sizes; (void)n_in; (void)out_size;
    const float* x   = (const float*)d_in[0];
    const int*   mask= (const int*)  d_in[1];
    const float* Wq  = (const float*)d_in[2];
    const float* bq  = (const float*)d_in[3];
    const float* Wk  = (const float*)d_in[4];
    const float* bk  = (const float*)d_in[5];
    const float* Wv  = (const float*)d_in[6];
    const float* bv  = (const float*)d_in[7];
    const float* Wo  = (const float*)d_in[8];
    const float* bo  = (const float*)d_in[9];
    const float* g1  = (const float*)d_in[10];
    const float* be1 = (const float*)d_in[11];
    const float* W1  = (const float*)d_in[12];
    const float* b1  = (const float*)d_in[13];
    const float* W2  = (const float*)d_in[14];
    const float* b2  = (const float*)d_in[15];
    const float* g2  = (const float*)d_in[16];
    const float* be2 = (const float*)d_in[17];

    float* out  = (float*)d_out;
    float* attn = out + (size_t)TOK*D_MODEL;

    bf16 *xh,*xl,*wqh,*wql,*wkh,*wkl,*wvh,*wvl,*woh,*wol,*w1h,*w1l,*w2h,*w2l;
    bf16 *qh,*ql,*kh,*kl,*vh,*vl,*vth,*vtl,*ah,*al,*ch,*cl,*hh,*hl,*ffh,*ffl;
    float *y,*h;
    cudaGetSymbolAddress((void**)&xh,g_xh);   cudaGetSymbolAddress((void**)&xl,g_xl);
    cudaGetSymbolAddress((void**)&wqh,g_wqh); cudaGetSymbolAddress((void**)&wql,g_wql);
    cudaGetSymbolAddress((void**)&wkh,g_wkh); cudaGetSymbolAddress((void**)&wkl,g_wkl);
    cudaGetSymbolAddress((void**)&wvh,g_wvh); cudaGetSymbolAddress((void**)&wvl,g_wvl);
    cudaGetSymbolAddress((void**)&woh,g_woh); cudaGetSymbolAddress((void**)&wol,g_wol);
    cudaGetSymbolAddress((void**)&w1h,g_w1h); cudaGetSymbolAddress((void**)&w1l,g_w1l);
    cudaGetSymbolAddress((void**)&w2h,g_w2h); cudaGetSymbolAddress((void**)&w2l,g_w2l);
    cudaGetSymbolAddress((void**)&qh,g_qh);   cudaGetSymbolAddress((void**)&ql,g_ql);
    cudaGetSymbolAddress((void**)&kh,g_kh);   cudaGetSymbolAddress((void**)&kl,g_kl);
    cudaGetSymbolAddress((void**)&vh,g_vh);   cudaGetSymbolAddress((void**)&vl,g_vl);
    cudaGetSymbolAddress((void**)&vth,g_vth); cudaGetSymbolAddress((void**)&vtl,g_vtl);
    cudaGetSymbolAddress((void**)&ah,g_ah);   cudaGetSymbolAddress((void**)&al,g_al);
    cudaGetSymbolAddress((void**)&ch,g_ch);   cudaGetSymbolAddress((void**)&cl,g_cl);
    cudaGetSymbolAddress((void**)&hh,g_hh);   cudaGetSymbolAddress((void**)&hl,g_hl);
    cudaGetSymbolAddress((void**)&ffh,g_ffh); cudaGetSymbolAddress((void**)&ffl,g_ffl);
    cudaGetSymbolAddress((void**)&y,g_y);     cudaGetSymbolAddress((void**)&h,g_h);

    // dynamic smem: 2 stages * 2*(SA+SB) bf16
    const int SM128 = 2 * 2*(128*40 + 128*40) * 2;  // 81920 B
    const int SM64  = 2 * 2*(128*40 + 64*40)  * 2;  // 61440 B
    cudaFuncSetAttribute(gemm_mma<128,1,false>, cudaFuncAttributeMaxDynamicSharedMemorySize, SM128);
    cudaFuncSetAttribute(gemm_mma<128,0,false>, cudaFuncAttributeMaxDynamicSharedMemorySize, SM128);
    cudaFuncSetAttribute(gemm_mma<128,1,true >, cudaFuncAttributeMaxDynamicSharedMemorySize, SM128);
    cudaFuncSetAttribute(gemm_mma<64 ,1,false>, cudaFuncAttributeMaxDynamicSharedMemorySize, SM64);

    const dim3 blk(256), tb(32,8);
    const long SD = (long)SEQ*D_MODEL, SS = (long)SEQ*SEQ;

    conv_pair_k<<<(TOK*D_MODEL)/256, blk>>>(x, xh, xl, (long)TOK*D_MODEL);
    wtrans_k<<<dim3(32,32),  tb>>>(Wq, wqh, wql, D_MODEL, D_MODEL);
    wtrans_k<<<dim3(32,32),  tb>>>(Wk, wkh, wkl, D_MODEL, D_MODEL);
    wtrans_k<<<dim3(32,32),  tb>>>(Wv, wvh, wvl, D_MODEL, D_MODEL);
    wtrans_k<<<dim3(32,32),  tb>>>(Wo, woh, wol, D_MODEL, D_MODEL);
    wtrans_k<<<dim3(128,32), tb>>>(W1, w1h, w1l, D_MODEL, D_FF);
    wtrans_k<<<dim3(32,128), tb>>>(W2, w2h, w2l, D_FF, D_MODEL);

    // QKV projections -> bf16 pairs
    gemm_mma<128,1,false><<<dim3(8,32,1), blk, SM128>>>(xh,xl, wqh,wql, bq, nullptr, qh,ql,
        D_MODEL, D_MODEL, D_MODEL, D_MODEL, 0,0,0,0,0,0, 1.f);
    gemm_mma<128,1,false><<<dim3(8,32,1), blk, SM128>>>(xh,xl, wkh,wkl, bk, nullptr, kh,kl,
        D_MODEL, D_MODEL, D_MODEL, D_MODEL, 0,0,0,0,0,0, 1.f);
    gemm_mma<128,1,false><<<dim3(8,32,1), blk, SM128>>>(xh,xl, wvh,wvl, bv, nullptr, vh,vl,
        D_MODEL, D_MODEL, D_MODEL, D_MODEL, 0,0,0,0,0,0, 1.f);

    // scores = Q K^T / 8 -> attn (fp32)
    gemm_mma<128,0,false><<<dim3(16,16,BH), blk, SM128>>>(qh,ql, kh,kl, nullptr, attn, nullptr,nullptr,
        D_K, D_MODEL, D_MODEL, SEQ, SD, (long)D_K, SD, (long)D_K, (long)NUM_HEADS*SS, SS, 0.125f);

    // softmax in-place + bf16 pairs
    softmax_k<<<BH*SEQ, blk>>>(attn, mask, ah, al);

    // V^T per head
    vtrans_k<<<dim3(SEQ/32, D_K/32, BH), tb>>>(vh, vl, vth, vtl);

    // ctx = attn @ V -> pairs in [B,S,D]
    gemm_mma<64,1,false><<<dim3(1,16,BH), blk, SM64>>>(ah,al, vth,vtl, nullptr, nullptr, ch,cl,
        SEQ, SEQ, SEQ, D_MODEL, (long)NUM_HEADS*SS, SS, (long)NUM_HEADS*D_K*SEQ, (long)D_K*SEQ, SD, (long)D_K, 1.f);

    // attn_out = ctx @ Wo + bo -> fp32 y
    gemm_mma<128,0,false><<<dim3(8,32,1), blk, SM128>>>(ch,cl, woh,wol, bo, y, nullptr,nullptr,
        D_MODEL, D_MODEL, D_MODEL, D_MODEL, 0,0,0,0,0,0, 1.f);

    // h = LN(x + y) -> fp32 + pairs
    add_ln_k<<<TOK, blk>>>(x, y, g1, be1, h, hh, hl);

    // ff = relu(h W1 + b1) -> pairs
    gemm_mma<128,1,true><<<dim3(32,32,1), blk, SM128>>>(hh,hl, w1h,w1l, b1, nullptr, ffh,ffl,
        D_MODEL, D_MODEL, D_MODEL, D_FF, 0,0,0,0,0,0, 1.f);

    // y = ff W2 + b2 -> fp32
    gemm_mma<128,0,false><<<dim3(8,32,1), blk, SM128>>>(ffh,ffl, w2h,w2l, b2, y, nullptr,nullptr,
        D_FF, D_FF, D_FF, D_MODEL, 0,0,0,0,0,0, 1.f);

    // out = LN(h + y)
    add_ln_k<<<TOK, blk>>>(h, y, g2, be2, out, nullptr, nullptr);
}

// round 5
// speedup vs baseline: 2.3548x; 1.0245x over previous
#include <cuda_runtime.h>
#include <cuda_bf16.h>
#include <cstdint>
#include <math.h>

#define D_MODEL 1024
#define NUM_HEADS 16
#define D_K 64
#define D_FF 4096
#define BATCH 2
#define SEQ 2048
#define TOK (BATCH*SEQ)
#define BH (BATCH*NUM_HEADS)
typedef __nv_bfloat16 bf16;

// ---- scratch ----
__device__ bf16 g_xh[(size_t)TOK*D_MODEL], g_xl[(size_t)TOK*D_MODEL];
__device__ bf16 g_wqh[(size_t)D_MODEL*D_MODEL], g_wql[(size_t)D_MODEL*D_MODEL];
__device__ bf16 g_wkh[(size_t)D_MODEL*D_MODEL], g_wkl[(size_t)D_MODEL*D_MODEL];
__device__ bf16 g_wvh[(size_t)D_MODEL*D_MODEL], g_wvl[(size_t)D_MODEL*D_MODEL];
__device__ bf16 g_woh[(size_t)D_MODEL*D_MODEL], g_wol[(size_t)D_MODEL*D_MODEL];
__device__ bf16 g_w1h[(size_t)D_FF*D_MODEL],  g_w1l[(size_t)D_FF*D_MODEL];
__device__ bf16 g_w2h[(size_t)D_MODEL*D_FF],  g_w2l[(size_t)D_MODEL*D_FF];
__device__ bf16 g_qh[(size_t)TOK*D_MODEL], g_ql[(size_t)TOK*D_MODEL];
__device__ bf16 g_kh[(size_t)TOK*D_MODEL], g_kl[(size_t)TOK*D_MODEL];
__device__ bf16 g_vh[(size_t)TOK*D_MODEL], g_vl[(size_t)TOK*D_MODEL];
__device__ bf16 g_vth[(size_t)BH*D_K*SEQ], g_vtl[(size_t)BH*D_K*SEQ];
__device__ bf16 g_ah[(size_t)BH*SEQ*SEQ],  g_al[(size_t)BH*SEQ*SEQ];
__device__ bf16 g_ch[(size_t)TOK*D_MODEL], g_cl[(size_t)TOK*D_MODEL];
__device__ bf16 g_hh[(size_t)TOK*D_MODEL], g_hl[(size_t)TOK*D_MODEL];
__device__ bf16 g_ffh[(size_t)TOK*D_FF],   g_ffl[(size_t)TOK*D_FF];
__device__ float g_y[(size_t)TOK*D_MODEL];
__device__ float g_h[(size_t)TOK*D_MODEL];

// ---- helpers ----
__device__ __forceinline__ uint32_t smem_u32(const void* p){
    uint32_t a;
    asm("{ .reg .u64 t; cvta.to.shared.u64 t, %1; cvt.u32.u64 %0, t; }" : "=r"(a) : "l"(p));
    return a;
}
__device__ __forceinline__ void f2pair(float f, bf16& h, bf16& l){
    h = __float2bfloat16(f);
    l = __float2bfloat16(f - __bfloat162float(h));
}
#define CP16(d, s) asm volatile("cp.async.cg.shared.global [%0], [%1], 16;" :: "r"(d), "l"(s))
#define CP_COMMIT() asm volatile("cp.async.commit_group;" ::: "memory")
#define MMA(c, a, b0, b1) \
    asm volatile("mma.sync.aligned.m16n8k16.row.col.f32.bf16.bf16.f32 " \
        "{%0,%1,%2,%3},{%4,%5,%6,%7},{%8,%9},{%0,%1,%2,%3};" \
        : "+f"((c)[0]),"+f"((c)[1]),"+f"((c)[2]),"+f"((c)[3]) \
        : "r"((a)[0]),"r"((a)[1]),"r"((a)[2]),"r"((a)[3]),"r"(b0),"r"(b1))
__device__ __forceinline__ void ldm4(uint32_t* r, uint32_t addr){
    asm volatile("ldmatrix.sync.aligned.m8n8.x4.shared.b16 {%0,%1,%2,%3}, [%4];"
        : "=r"(r[0]),"=r"(r[1]),"=r"(r[2]),"=r"(r[3]) : "r"(addr));
}

// ---- conversions ----
__global__ void conv_pair_k(const float* __restrict__ s, bf16* __restrict__ h, bf16* __restrict__ l, long n){
    long i = (long)blockIdx.x*blockDim.x + threadIdx.x;
    if(i < n){ bf16 a,b; f2pair(s[i],a,b); h[i]=a; l[i]=b; }
}
__global__ void wtrans_k(const float* __restrict__ W, bf16* __restrict__ th, bf16* __restrict__ tl, int K, int N){
    __shared__ float t[32][33];
    int n0 = blockIdx.x*32, k0 = blockIdx.y*32;
#pragma unroll
    for(int r=0;r<4;r++) t[threadIdx.y+r*8][threadIdx.x] = W[(long)(k0+threadIdx.y+r*8)*N + n0+threadIdx.x];
    __syncthreads();
#pragma unroll
    for(int r=0;r<4;r++){
        int n = n0+threadIdx.y+r*8;
        bf16 a,b; f2pair(t[threadIdx.x][threadIdx.y+r*8],a,b);
        th[(long)n*K + k0+threadIdx.x]=a; tl[(long)n*K + k0+threadIdx.x]=b;
    }
}
__global__ void vtrans_k(const bf16* __restrict__ vh, const bf16* __restrict__ vl,
                         bf16* __restrict__ oth, bf16* __restrict__ otl){
    __shared__ bf16 th_[32][33], tl_[32][33];
    int bz = blockIdx.z, bb = bz/NUM_HEADS, hh = bz%NUM_HEADS;
    int s0 = blockIdx.x*32, n0 = blockIdx.y*32;
#pragma unroll
    for(int r=0;r<4;r++){
        long src = (long)(bb*SEQ + s0+threadIdx.y+r*8)*D_MODEL + hh*D_K + n0+threadIdx.x;
        th_[threadIdx.y+r*8][threadIdx.x] = vh[src];
        tl_[threadIdx.y+r*8][threadIdx.x] = vl[src];
    }
    __syncthreads();
#pragma unroll
    for(int r=0;r<4;r++){
        long dst = ((long)bz*D_K + n0+threadIdx.y+r*8)*SEQ + s0+threadIdx.x;
        oth[dst] = th_[threadIdx.x][threadIdx.y+r*8];
        otl[dst] = tl_[threadIdx.x][threadIdx.y+r*8];
    }
}

// ---- split-bf16 GEMM via mma.sync + ldmatrix: C = alpha*A[M,K]*B[N,K]^T ----
// 256 thr = 8 warps (4m x 2n). Block tile 128 x TN, BK=32, 2-stage cp.async pipe.
template<int TN, int OUT, bool RELU>
__global__ void __launch_bounds__(256) gemm_mma(
    const bf16* __restrict__ Ah, const bf16* __restrict__ Al,
    const bf16* __restrict__ Bh, const bf16* __restrict__ Bl,
    const float* __restrict__ bias,
    float* __restrict__ Cf, bf16* __restrict__ Ch, bf16* __restrict__ Cl,
    int K, int lda, int ldb, int ldc,
    long sAb, long sAhd, long sBb, long sBhd, long sCb, long sChd, float alpha)
{
    constexpr int PADK = 40;
    constexpr int SA = 128*PADK;
    constexpr int SB = TN*PADK;
    constexpr int STG = 2*(SA+SB);
    constexpr int NTILES = TN/16;            // 8 or 4
    constexpr int NP = NTILES/2;             // ldmatrix nt pairs
    constexpr int BCH = (TN==128) ? 2 : 1;

    extern __shared__ bf16 sm[];
    const int tid = threadIdx.x, wid = tid>>5, lane = tid&31;
    const int warp_m = wid & 3, warp_n = wid >> 2;
    const int g = lane>>2, t2 = (lane&3)*2;

    const int bz = blockIdx.z, bb = bz/NUM_HEADS, hh = bz%NUM_HEADS;
    Ah += bb*sAb + hh*sAhd;  Al += bb*sAb + hh*sAhd;
    Bh += bb*sBb + hh*sBhd;  Bl += bb*sBb + hh*sBhd;
    const long coff = bb*sCb + hh*sChd;
    const int row0 = blockIdx.y*128, col0 = blockIdx.x*TN;

    // ldmatrix per-lane element offsets (column part added per k-step)
    // A x4 matrix order: (m0-7,k0-7),(m8-15,k0-7),(m0-7,k8-15),(m8-15,k8-15)
    int aoff[2];
#pragma unroll
    for(int mt=0; mt<2; mt++)
        aoff[mt] = (warp_m*32 + mt*16 + (lane&7) + ((lane>>3)&1)*8)*PADK + ((lane>>4)<<3);
    // B x4 matrix order: (nt0,k0-7),(nt0,k8-15),(nt1,k0-7),(nt1,k8-15)
    int boff[NP];
#pragma unroll
    for(int p=0; p<NP; p++)
        boff[p] = (warp_n*(TN/2) + p*16 + ((lane>>4)<<3) + (lane&7))*PADK + ((lane>>3)&1)*8;

    float acc[2][NTILES][4];
#pragma unroll
    for(int i=0;i<2;i++)
#pragma unroll
        for(int j=0;j<NTILES;j++)
#pragma unroll
            for(int e=0;e<4;e++) acc[i][j][e]=0.f;

    const int NT = K/32;

    auto issue = [&](int stage, int kb){
        bf16* st = sm + (stage&1)*STG;
#pragma unroll
        for(int c=0;c<2;c++){
            int cid = tid*2+c, r = cid>>2, k8 = (cid&3)*8;
            CP16(smem_u32(st + r*PADK + k8),      Ah + (long)(row0+r)*lda + kb + k8);
            CP16(smem_u32(st + SA + r*PADK + k8), Al + (long)(row0+r)*lda + kb + k8);
        }
#pragma unroll
        for(int c=0;c<BCH;c++){
            int cid = tid*BCH+c, n = cid>>2, k8 = (cid&3)*8;
            CP16(smem_u32(st + 2*SA + n*PADK + k8),      Bh + (long)(col0+n)*ldb + kb + k8);
            CP16(smem_u32(st + 2*SA + SB + n*PADK + k8), Bl + (long)(col0+n)*ldb + kb + k8);
        }
        CP_COMMIT();
    };

    auto compute = [&](int stage){
        const uint32_t uAh = smem_u32(sm + (stage&1)*STG);
        const uint32_t uAl = uAh + SA*2;
        const uint32_t uBh = uAh + 2*SA*2;
        const uint32_t uBl = uAh + (2*SA+SB)*2;
#pragma unroll
        for(int ks=0; ks<2; ks++){
            const int kc = ks*16;
            uint32_t fAh[2][4], fAl[2][4];
#pragma unroll
            for(int mt=0; mt<2; mt++){
                ldm4(fAh[mt], uAh + (aoff[mt]+kc)*2);
                ldm4(fAl[mt], uAl + (aoff[mt]+kc)*2);
            }
#pragma unroll
            for(int p=0; p<NP; p++){
                uint32_t bh[4], bl[4];
                ldm4(bh, uBh + (boff[p]+kc)*2);
                ldm4(bl, uBl + (boff[p]+kc)*2);
#pragma unroll
                for(int s=0; s<2; s++){
                    const int nt = p*2 + s;
#pragma unroll
                    for(int mt=0; mt<2; mt++){
                        MMA(acc[mt][nt], fAh[mt], bh[s*2], bh[s*2+1]);
                        MMA(acc[mt][nt], fAh[mt], bl[s*2], bl[s*2+1]);
                        MMA(acc[mt][nt], fAl[mt], bh[s*2], bh[s*2+1]);
                    }
                }
            }
        }
    };

    issue(0, 0);
    if(NT > 1) issue(1, 32);

    for(int i=0; i<NT; i++){
        if(i+1 < NT) asm volatile("cp.async.wait_group 1;" ::: "memory");
        else         asm volatile("cp.async.wait_group 0;" ::: "memory");
        __syncthreads();
        compute(i);
        if(i+2 < NT){
            __syncthreads();
            issue(i+2, (i+2)*32);
        }
    }

    // ---- epilogue ----
#pragma unroll
    for(int mt=0; mt<2; mt++){
#pragma unroll
        for(int nt=0; nt<NTILES; nt++){
            int r = row0 + warp_m*32 + mt*16 + g;
            int c = col0 + warp_n*(TN/2) + nt*8 + t2;
            float b0 = bias ? bias[c]   : 0.f;
            float b1 = bias ? bias[c+1] : 0.f;
#pragma unroll
            for(int half=0; half<2; half++){
                int rr = r + half*8;
                float v0 = acc[mt][nt][half*2+0]*alpha + b0;
                float v1 = acc[mt][nt][half*2+1]*alpha + b1;
                if(RELU){ v0 = fmaxf(v0,0.f); v1 = fmaxf(v1,0.f); }
                long idx = coff + (long)rr*ldc + c;
                if(OUT==0){
                    *(float2*)(Cf + idx) = make_float2(v0, v1);
                } else {
                    bf16 h0,l0,h1,l1; f2pair(v0,h0,l0); f2pair(v1,h1,l1);
                    *(__nv_bfloat162*)(Ch + idx) = __nv_bfloat162(h0, h1);
                    *(__nv_bfloat162*)(Cl + idx) = __nv_bfloat162(l0, l1);
                }
            }
        }
    }
}

// ---- softmax: in-place fp32 + bf16 pair out ----
__launch_bounds__(256)
__global__ void softmax_k(float* __restrict__ attn, const int* __restrict__ mask,
                          bf16* __restrict__ ah, bf16* __restrict__ al){
    const long row = blockIdx.x;
    const int b = (int)(row / ((long)NUM_HEADS*SEQ));
    float* p = attn + row*SEQ;
    const int* m = mask + (long)b*SEQ;
    const int tid = threadIdx.x;
    __shared__ float sred[8]; __shared__ float sbc;
    float vals[8]; float mx = -1e30f;
#pragma unroll
    for(int t=0;t<8;t++){ int j=tid+t*256; float vv=p[j]; if(m[j]==0) vv=-1e9f; vals[t]=vv; mx=fmaxf(mx,vv); }
#pragma unroll
    for(int o=16;o;o>>=1) mx = fmaxf(mx, __shfl_xor_sync(0xffffffffu, mx, o));
    if((tid&31)==0) sred[tid>>5]=mx;
    __syncthreads();
    if(tid==0){ float r=sred[0]; for(int i=1;i<8;i++) r=fmaxf(r,sred[i]); sbc=r; }
    __syncthreads();
    mx = sbc;
    float sum = 0.f;
#pragma unroll
    for(int t=0;t<8;t++){ vals[t]=__expf(vals[t]-mx); sum+=vals[t]; }
#pragma unroll
    for(int o=16;o;o>>=1) sum += __shfl_xor_sync(0xffffffffu, sum, o);
    __syncthreads();
    if((tid&31)==0) sred[tid>>5]=sum;
    __syncthreads();
    if(tid==0){ float r=0.f; for(int i=0;i<8;i++) r+=sred[i]; sbc=1.f/r; }
    __syncthreads();
    const float inv = sbc;
    bf16* pah = ah + row*SEQ; bf16* pal = al + row*SEQ;
#pragma unroll
    for(int t=0;t<8;t++){
        int j=tid+t*256; float v=vals[t]*inv; p[j]=v;
        bf16 h,l; f2pair(v,h,l); pah[j]=h; pal[j]=l;
    }
}

// ---- add + LN (+ optional pair out) ----
__launch_bounds__(256)
__global__ void add_ln_k(const float* __restrict__ a, const float* __restrict__ bres,
                         const float* __restrict__ g, const float* __restrict__ be,
                         float* __restrict__ outp, bf16* __restrict__ ph, bf16* __restrict__ pl){
    const long row = blockIdx.x;
    const float* pa = a + row*D_MODEL;
    const float* pb = bres + row*D_MODEL;
    const int tid = threadIdx.x;
    __shared__ float sred[8]; __shared__ float sbc;
    float v[4]; float s = 0.f;
#pragma unroll
    for(int t=0;t<4;t++){ int c=tid+t*256; v[t]=pa[c]+pb[c]; s+=v[t]; }
#pragma unroll
    for(int o=16;o;o>>=1) s += __shfl_xor_sync(0xffffffffu, s, o);
    if((tid&31)==0) sred[tid>>5]=s;
    __syncthreads();
    if(tid==0){ float r=0.f; for(int i=0;i<8;i++) r+=sred[i]; sbc=r*(1.f/D_MODEL); }
    __syncthreads();
    const float mu = sbc;
    float q = 0.f;
#pragma unroll
    for(int t=0;t<4;t++){ float d=v[t]-mu; q+=d*d; }
#pragma unroll
    for(int o=16;o;o>>=1) q += __shfl_xor_sync(0xffffffffu, q, o);
    __syncthreads();
    if((tid&31)==0) sred[tid>>5]=q;
    __syncthreads();
    if(tid==0){ float r=0.f; for(int i=0;i<8;i++) r+=sred[i]; sbc=rsqrtf(r*(1.f/D_MODEL)+1e-5f); }
    __syncthreads();
    const float rstd = sbc;
#pragma unroll
    for(int t=0;t<4;t++){
        int c = tid+t*256;
        float o = (v[t]-mu)*rstd*g[c] + be[c];
        outp[row*D_MODEL+c] = o;
        if(ph){ bf16 h,l; f2pair(o,h,l); ph[row*D_MODEL+c]=h; pl[row*D_MODEL+c]=l; }
    }
}

// -----------------------------------------------------------------------------------
extern "C" void kernel_launch(void* const* d_in, const int* in_sizes, int n_in,
                              void* d_out, int out_size)
{
    (void)in_sizes; (void)n_in; (void)out_size;
    const float* x   = (const float*)d_in[0];
    const int*   mask= (const int*)  d_in[1];
    const float* Wq  = (const float*)d_in[2];
    const float* bq  = (const float*)d_in[3];
    const float* Wk  = (const float*)d_in[4];
    const float* bk  = (const float*)d_in[5];
    const float* Wv  = (const float*)d_in[6];
    const float* bv  = (const float*)d_in[7];
    const float* Wo  = (const float*)d_in[8];
    const float* bo  = (const float*)d_in[9];
    const float* g1  = (const float*)d_in[10];
    const float* be1 = (const float*)d_in[11];
    const float* W1  = (const float*)d_in[12];
    const float* b1  = (const float*)d_in[13];
    const float* W2  = (const float*)d_in[14];
    const float* b2  = (const float*)d_in[15];
    const float* g2  = (const float*)d_in[16];
    const float* be2 = (const float*)d_in[17];

    float* out  = (float*)d_out;
    float* attn = out + (size_t)TOK*D_MODEL;

    bf16 *xh,*xl,*wqh,*wql,*wkh,*wkl,*wvh,*wvl,*woh,*wol,*w1h,*w1l,*w2h,*w2l;
    bf16 *qh,*ql,*kh,*kl,*vh,*vl,*vth,*vtl,*ah,*al,*ch,*cl,*hh,*hl,*ffh,*ffl;
    float *y,*h;
    cudaGetSymbolAddress((void**)&xh,g_xh);   cudaGetSymbolAddress((void**)&xl,g_xl);
    cudaGetSymbolAddress((void**)&wqh,g_wqh); cudaGetSymbolAddress((void**)&wql,g_wql);
    cudaGetSymbolAddress((void**)&wkh,g_wkh); cudaGetSymbolAddress((void**)&wkl,g_wkl);
    cudaGetSymbolAddress((void**)&wvh,g_wvh); cudaGetSymbolAddress((void**)&wvl,g_wvl);
    cudaGetSymbolAddress((void**)&woh,g_woh); cudaGetSymbolAddress((void**)&wol,g_wol);
    cudaGetSymbolAddress((void**)&w1h,g_w1h); cudaGetSymbolAddress((void**)&w1l,g_w1l);
    cudaGetSymbolAddress((void**)&w2h,g_w2h); cudaGetSymbolAddress((void**)&w2l,g_w2l);
    cudaGetSymbolAddress((void**)&qh,g_qh);   cudaGetSymbolAddress((void**)&ql,g_ql);
    cudaGetSymbolAddress((void**)&kh,g_kh);   cudaGetSymbolAddress((void**)&kl,g_kl);
    cudaGetSymbolAddress((void**)&vh,g_vh);   cudaGetSymbolAddress((void**)&vl,g_vl);
    cudaGetSymbolAddress((void**)&vth,g_vth); cudaGetSymbolAddress((void**)&vtl,g_vtl);
    cudaGetSymbolAddress((void**)&ah,g_ah);   cudaGetSymbolAddress((void**)&al,g_al);
    cudaGetSymbolAddress((void**)&ch,g_ch);   cudaGetSymbolAddress((void**)&cl,g_cl);
    cudaGetSymbolAddress((void**)&hh,g_hh);   cudaGetSymbolAddress((void**)&hl,g_hl);
    cudaGetSymbolAddress((void**)&ffh,g_ffh); cudaGetSymbolAddress((void**)&ffl,g_ffl);
    cudaGetSymbolAddress((void**)&y,g_y);     cudaGetSymbolAddress((void**)&h,g_h);

    const int SM128 = 2 * 2*(128*40 + 128*40) * 2;  // 81920 B
    const int SM64  = 2 * 2*(128*40 + 64*40)  * 2;  // 61440 B
    cudaFuncSetAttribute(gemm_mma<128,1,false>, cudaFuncAttributeMaxDynamicSharedMemorySize, SM128);
    cudaFuncSetAttribute(gemm_mma<128,0,false>, cudaFuncAttributeMaxDynamicSharedMemorySize, SM128);
    cudaFuncSetAttribute(gemm_mma<128,1,true >, cudaFuncAttributeMaxDynamicSharedMemorySize, SM128);
    cudaFuncSetAttribute(gemm_mma<64 ,1,false>, cudaFuncAttributeMaxDynamicSharedMemorySize, SM64);

    const dim3 blk(256), tb(32,8);
    const long SD = (long)SEQ*D_MODEL, SS = (long)SEQ*SEQ;

    conv_pair_k<<<(TOK*D_MODEL)/256, blk>>>(x, xh, xl, (long)TOK*D_MODEL);
    wtrans_k<<<dim3(32,32),  tb>>>(Wq, wqh, wql, D_MODEL, D_MODEL);
    wtrans_k<<<dim3(32,32),  tb>>>(Wk, wkh, wkl, D_MODEL, D_MODEL);
    wtrans_k<<<dim3(32,32),  tb>>>(Wv, wvh, wvl, D_MODEL, D_MODEL);
    wtrans_k<<<dim3(32,32),  tb>>>(Wo, woh, wol, D_MODEL, D_MODEL);
    wtrans_k<<<dim3(128,32), tb>>>(W1, w1h, w1l, D_MODEL, D_FF);
    wtrans_k<<<dim3(32,128), tb>>>(W2, w2h, w2l, D_FF, D_MODEL);

    gemm_mma<128,1,false><<<dim3(8,32,1), blk, SM128>>>(xh,xl, wqh,wql, bq, nullptr, qh,ql,
        D_MODEL, D_MODEL, D_MODEL, D_MODEL, 0,0,0,0,0,0, 1.f);
    gemm_mma<128,1,false><<<dim3(8,32,1), blk, SM128>>>(xh,xl, wkh,wkl, bk, nullptr, kh,kl,
        D_MODEL, D_MODEL, D_MODEL, D_MODEL, 0,0,0,0,0,0, 1.f);
    gemm_mma<128,1,false><<<dim3(8,32,1), blk, SM128>>>(xh,xl, wvh,wvl, bv, nullptr, vh,vl,
        D_MODEL, D_MODEL, D_MODEL, D_MODEL, 0,0,0,0,0,0, 1.f);

    gemm_mma<128,0,false><<<dim3(16,16,BH), blk, SM128>>>(qh,ql, kh,kl, nullptr, attn, nullptr,nullptr,
        D_K, D_MODEL, D_MODEL, SEQ, SD, (long)D_K, SD, (long)D_K, (long)NUM_HEADS*SS, SS, 0.125f);

    softmax_k<<<BH*SEQ, blk>>>(attn, mask, ah, al);

    vtrans_k<<<dim3(SEQ/32, D_K/32, BH), tb>>>(vh, vl, vth, vtl);

    gemm_mma<64,1,false><<<dim3(1,16,BH), blk, SM64>>>(ah,al, vth,vtl, nullptr, nullptr, ch,cl,
        SEQ, SEQ, SEQ, D_MODEL, (long)NUM_HEADS*SS, SS, (long)NUM_HEADS*D_K*SEQ, (long)D_K*SEQ, SD, (long)D_K, 1.f);

    gemm_mma<128,0,false><<<dim3(8,32,1), blk, SM128>>>(ch,cl, woh,wol, bo, y, nullptr,nullptr,
        D_MODEL, D_MODEL, D_MODEL, D_MODEL, 0,0,0,0,0,0, 1.f);

    add_ln_k<<<TOK, blk>>>(x, y, g1, be1, h, hh, hl);

    gemm_mma<128,1,true><<<dim3(32,32,1), blk, SM128>>>(hh,hl, w1h,w1l, b1, nullptr, ffh,ffl,
        D_MODEL, D_MODEL, D_MODEL, D_FF, 0,0,0,0,0,0, 1.f);

    gemm_mma<128,0,false><<<dim3(8,32,1), blk, SM128>>>(ffh,ffl, w2h,w2l, b2, y, nullptr,nullptr,
        D_FF, D_FF, D_FF, D_MODEL, 0,0,0,0,0,0, 1.f);

    add_ln_k<<<TOK, blk>>>(h, y, g2, be2, out, nullptr, nullptr);
}